// round 3
// baseline (speedup 1.0000x reference)
#include <cuda_runtime.h>
#include <cuda_bf16.h>
#include <cstdint>
#include <cstddef>

#define FULLMASK 0xffffffffu

namespace cfg {
constexpr int B = 4, N = 16384, S = 2048, K = 32;
constexpr int NN = B * S * K;           // 262144 columns
constexpr int BS = B * S;               // 8192 groups
constexpr float R2 = 0.2f * 0.2f;
constexpr float EPS = 1e-5f;
}

// ---------------- static scratch (no allocations allowed) ----------------
__device__ int   g_idxc[cfg::BS];
__device__ float g_newxyz[cfg::BS * 3];
__device__ int   g_ballidx[(size_t)cfg::BS * cfg::K];
__device__ float g_x1[(size_t)64  * cfg::NN];   //  64 MB
__device__ float g_x2[(size_t)128 * cfg::NN];   // 128 MB
__device__ float g_x3[(size_t)256 * cfg::NN];   // 256 MB
__device__ float g_psum[256 * 64];
__device__ float g_psq [256 * 64];
__device__ float g_A [256];
__device__ float g_Bc[256];

// =====================================================================
// 1) Farthest point sampling: 8-CTA cluster per batch, 2 pts/thread.
// =====================================================================
__global__ void __cluster_dims__(8, 1, 1) __launch_bounds__(1024, 1)
fps_kernel(const float* __restrict__ pos)
{
    using namespace cfg;
    const int batch = blockIdx.x >> 3;
    const int rank  = blockIdx.x & 7;
    const int tid   = threadIdx.x;
    const int lane  = tid & 31;
    const int wid   = tid >> 5;

    const float* pb = pos + (size_t)batch * N * 3;
    const int i0 = rank * 2048 + tid;
    const int i1 = i0 + 1024;

    float px0 = pb[i0 * 3 + 0], py0 = pb[i0 * 3 + 1], pz0 = pb[i0 * 3 + 2];
    float px1 = pb[i1 * 3 + 0], py1 = pb[i1 * 3 + 1], pz1 = pb[i1 * 3 + 2];
    float d0 = 1e10f, d1 = 1e10f;

    __shared__ unsigned long long s_warp[32];
    __shared__ unsigned long long s_block;
    __shared__ unsigned long long s_ckey[2][8];
    __shared__ float s_cx[2][8], s_cy[2][8], s_cz[2][8];

    float cx = pb[0], cy = pb[1], cz = pb[2];   // first centroid = point 0
    unsigned far = 0u;

    for (int s = 0; s < S; ++s) {
        if (rank == 0 && tid == 0) g_idxc[batch * S + s] = (int)far;

        // distance update — mirror reference: (dx*dx + dy*dy) + dz*dz, no fma
        {
            float dx = __fadd_rn(px0, -cx), dy = __fadd_rn(py0, -cy), dz = __fadd_rn(pz0, -cz);
            float t = __fadd_rn(__fadd_rn(__fmul_rn(dx, dx), __fmul_rn(dy, dy)), __fmul_rn(dz, dz));
            d0 = fminf(d0, t);
            dx = __fadd_rn(px1, -cx); dy = __fadd_rn(py1, -cy); dz = __fadd_rn(pz1, -cz);
            t = __fadd_rn(__fadd_rn(__fmul_rn(dx, dx), __fmul_rn(dy, dy)), __fmul_rn(dz, dz));
            d1 = fminf(d1, t);
        }

        // warp argmax: max dist, tie -> min index (matches jnp.argmax)
        unsigned b0 = __float_as_uint(d0), b1 = __float_as_uint(d1);
        unsigned wb = __reduce_max_sync(FULLMASK, b0 > b1 ? b0 : b1);
        unsigned ci = 0x7fffffffu;
        if (b0 == wb)      ci = (unsigned)i0;
        else if (b1 == wb) ci = (unsigned)i1;
        unsigned wi = __reduce_min_sync(FULLMASK, ci);
        if (lane == 0)
            s_warp[wid] = ((unsigned long long)wb << 32) |
                          (unsigned long long)(0xffffffffu - wi);
        __syncthreads();
        if (wid == 0) {
            unsigned long long k = s_warp[lane];
#pragma unroll
            for (int off = 16; off; off >>= 1) {
                unsigned long long o = __shfl_xor_sync(FULLMASK, k, off);
                if (o > k) k = o;
            }
            if (lane == 0) s_block = k;
        }
        __syncthreads();
        const unsigned long long bb = s_block;
        const unsigned bi = 0xffffffffu - (unsigned)bb;
        const int par = s & 1;

        // thread owning this CTA's winner publishes (key, coords) to all CTAs
        if (bi == (unsigned)i0 || bi == (unsigned)i1) {
            float wx, wy, wz;
            if (bi == (unsigned)i0) { wx = px0; wy = py0; wz = pz0; }
            else                    { wx = px1; wy = py1; wz = pz1; }
            unsigned a_k = (unsigned)__cvta_generic_to_shared(&s_ckey[par][rank]);
            unsigned a_x = (unsigned)__cvta_generic_to_shared(&s_cx[par][rank]);
            unsigned a_y = (unsigned)__cvta_generic_to_shared(&s_cy[par][rank]);
            unsigned a_z = (unsigned)__cvta_generic_to_shared(&s_cz[par][rank]);
#pragma unroll
            for (int r = 0; r < 8; ++r) {
                unsigned rk, rx, ry, rz;
                asm volatile("mapa.shared::cluster.u32 %0, %1, %2;" : "=r"(rk) : "r"(a_k), "r"(r));
                asm volatile("mapa.shared::cluster.u32 %0, %1, %2;" : "=r"(rx) : "r"(a_x), "r"(r));
                asm volatile("mapa.shared::cluster.u32 %0, %1, %2;" : "=r"(ry) : "r"(a_y), "r"(r));
                asm volatile("mapa.shared::cluster.u32 %0, %1, %2;" : "=r"(rz) : "r"(a_z), "r"(r));
                asm volatile("st.shared::cluster.u64 [%0], %1;" :: "r"(rk), "l"(bb) : "memory");
                asm volatile("st.shared::cluster.b32 [%0], %1;" :: "r"(rx), "r"(__float_as_uint(wx)) : "memory");
                asm volatile("st.shared::cluster.b32 [%0], %1;" :: "r"(ry), "r"(__float_as_uint(wy)) : "memory");
                asm volatile("st.shared::cluster.b32 [%0], %1;" :: "r"(rz), "r"(__float_as_uint(wz)) : "memory");
            }
        }
        asm volatile("barrier.cluster.arrive.aligned;" ::: "memory");
        asm volatile("barrier.cluster.wait.aligned;"   ::: "memory");

        unsigned long long bestk = 0ull; int bestr = 0;
#pragma unroll
        for (int r = 0; r < 8; ++r) {
            unsigned long long kk = s_ckey[par][r];
            if (kk > bestk) { bestk = kk; bestr = r; }
        }
        cx = s_cx[par][bestr]; cy = s_cy[par][bestr]; cz = s_cz[par][bestr];
        far = 0xffffffffu - (unsigned)bestk;
    }
}

// =====================================================================
// 2) gather centroids: new_xyz + transposed block of the output
// =====================================================================
__global__ void __launch_bounds__(256)
gather_kernel(const float* __restrict__ pos, float* __restrict__ out)
{
    using namespace cfg;
    int t = blockIdx.x * 256 + threadIdx.x;       // b*S+s
    int b = t / S, s = t - b * S;
    int id = g_idxc[t];
    const float* p = pos + ((size_t)b * N + id) * 3;
    float x = p[0], y = p[1], z = p[2];
    g_newxyz[t * 3 + 0] = x;
    g_newxyz[t * 3 + 1] = y;
    g_newxyz[t * 3 + 2] = z;
    out[((size_t)b * 3 + 0) * S + s] = x;
    out[((size_t)b * 3 + 1) * S + s] = y;
    out[((size_t)b * 3 + 2) * S + s] = z;
}

// =====================================================================
// 3) ball query: warp per centroid; first K in-radius indices ascending
// =====================================================================
__global__ void __launch_bounds__(256)
ballq_kernel(const float* __restrict__ pos)
{
    using namespace cfg;
    int g = blockIdx.x * 8 + (threadIdx.x >> 5);  // b*S+s
    int lane = threadIdx.x & 31;
    int b = g / S;
    float cx = g_newxyz[g * 3 + 0];
    float cy = g_newxyz[g * 3 + 1];
    float cz = g_newxyz[g * 3 + 2];
    float cn = __fadd_rn(__fadd_rn(__fmul_rn(cx, cx), __fmul_rn(cy, cy)), __fmul_rn(cz, cz));
    const float* pb = pos + (size_t)b * N * 3;
    int* outp = g_ballidx + (size_t)g * K;

    int filled = 0;
    int first = -1;
    for (int p0 = 0; p0 < N && filled < K; p0 += 32) {
        int p = p0 + lane;
        float px = pb[p * 3 + 0], py = pb[p * 3 + 1], pz = pb[p * 3 + 2];
        float pn = __fadd_rn(__fadd_rn(__fmul_rn(px, px), __fmul_rn(py, py)), __fmul_rn(pz, pz));
        float dot = __fadd_rn(__fadd_rn(__fmul_rn(cx, px), __fmul_rn(cy, py)), __fmul_rn(cz, pz));
        float sq = __fadd_rn(__fadd_rn(cn, pn), -__fmul_rn(2.0f, dot));
        bool incl = !(sq > R2);
        unsigned mask = __ballot_sync(FULLMASK, incl);
        if (first < 0 && mask) first = p0 + (__ffs(mask) - 1);
        int rnk = filled + __popc(mask & ((1u << lane) - 1u));
        if (incl && rnk < K) outp[rnk] = p;
        filled += __popc(mask);
    }
    if (first < 0) first = 0;
    if (filled < K)
        for (int j = filled + lane; j < K; j += 32) outp[j] = first;
}

// =====================================================================
// 4) layer1: gather groups + conv 6->64 (raw conv output, bias included)
// =====================================================================
__global__ void __launch_bounds__(256)
layer1_kernel(const float* __restrict__ pos, const float* __restrict__ feats,
              const float* __restrict__ w1, const float* __restrict__ b1)
{
    using namespace cfg;
    __shared__ float ws[64 * 6];
    __shared__ float bs[64];
    for (int i = threadIdx.x; i < 64 * 6; i += 256) ws[i] = w1[i];
    if (threadIdx.x < 64) bs[threadIdx.x] = b1[threadIdx.x];
    __syncthreads();

    int g = blockIdx.x * 8 + (threadIdx.x >> 5);  // b*S+s
    int lane = threadIdx.x & 31;                  // k within group
    int b = g / S;
    int id = g_ballidx[(size_t)g * K + lane];
    const float* p = pos   + ((size_t)b * N + id) * 3;
    const float* f = feats + ((size_t)b * N + id) * 3;
    float c0 = p[0] - g_newxyz[g * 3 + 0];
    float c1 = p[1] - g_newxyz[g * 3 + 1];
    float c2 = p[2] - g_newxyz[g * 3 + 2];
    float c3 = f[0], c4 = f[1], c5 = f[2];
    size_t ncol = (size_t)g * K + lane;
#pragma unroll
    for (int o = 0; o < 64; ++o) {
        const float* w = ws + o * 6;
        float acc = bs[o];
        acc = fmaf(w[0], c0, acc);
        acc = fmaf(w[1], c1, acc);
        acc = fmaf(w[2], c2, acc);
        acc = fmaf(w[3], c3, acc);
        acc = fmaf(w[4], c4, acc);
        acc = fmaf(w[5], c5, acc);
        g_x1[(size_t)o * NN + ncol] = acc;
    }
}

// =====================================================================
// 5) per-channel partial sums. LAYER selects the buffer IN DEVICE CODE
//    (host-passed __device__ symbols resolve to host shadows -> R2 bug)
// =====================================================================
template<int LAYER>
__global__ void __launch_bounds__(256)
stats_part_kernel()
{
    using namespace cfg;
    const float* x;
    if constexpr (LAYER == 1) x = g_x1;
    else if constexpr (LAYER == 2) x = g_x2;
    else x = g_x3;
    int c = blockIdx.y, chunk = blockIdx.x;
    const float* p = x + (size_t)c * NN + (size_t)chunk * 4096;
    int t = threadIdx.x;
    float s = 0.f, q = 0.f;
#pragma unroll
    for (int i = 0; i < 4; ++i) {
        float4 v = *(const float4*)&p[i * 1024 + t * 4];
        s += v.x; s += v.y; s += v.z; s += v.w;
        q += v.x * v.x; q += v.y * v.y; q += v.z * v.z; q += v.w * v.w;
    }
#pragma unroll
    for (int off = 16; off; off >>= 1) {
        s += __shfl_down_sync(FULLMASK, s, off);
        q += __shfl_down_sync(FULLMASK, q, off);
    }
    __shared__ float ss[8], qq[8];
    if ((t & 31) == 0) { ss[t >> 5] = s; qq[t >> 5] = q; }
    __syncthreads();
    if (t == 0) {
        float S2 = 0.f, Q2 = 0.f;
#pragma unroll
        for (int i = 0; i < 8; ++i) { S2 += ss[i]; Q2 += qq[i]; }
        g_psum[c * 64 + chunk] = S2;
        g_psq [c * 64 + chunk] = Q2;
    }
}

// finalize: mu, var -> folded scale/shift  y = relu(A*x + Bc)
__global__ void __launch_bounds__(256)
stats_fin_kernel(const float* __restrict__ gamma, const float* __restrict__ beta, int C)
{
    using namespace cfg;
    int c = blockIdx.x * 256 + threadIdx.x;
    if (c >= C) return;
    float s = 0.f, q = 0.f;
#pragma unroll 8
    for (int i = 0; i < 64; ++i) { s += g_psum[c * 64 + i]; q += g_psq[c * 64 + i]; }
    const float inv = 1.0f / (float)NN;   // 2^-18, exact
    float mu  = s * inv;
    float var = q * inv - mu * mu;
    float rs  = rsqrtf(var + EPS);
    float A   = gamma[c] * rs;
    g_A[c]  = A;
    g_Bc[c] = beta[c] - mu * A;
}

// =====================================================================
// 6) GEMM: Y = W * relu(A*X + Bc) + bias ; buffers chosen in device code
//    128x128 block tile, 8x8 micro tile, K step 8
// =====================================================================
template<int LAYER>
__global__ void __launch_bounds__(256)
gemm_kernel(const float* __restrict__ W, const float* __restrict__ bias)
{
    using namespace cfg;
    constexpr int Cin = (LAYER == 2) ? 64 : 128;
    const float* __restrict__ X = (LAYER == 2) ? g_x1 : g_x2;
    float* __restrict__ Y       = (LAYER == 2) ? g_x2 : g_x3;

    __shared__ float sA[8][128];
    __shared__ float sB[8][132];
    const int tid = threadIdx.x;
    const int n0 = blockIdx.x * 128;
    const int m0 = blockIdx.y * 128;
    const int tm = (tid >> 4) << 3;
    const int tn = (tid & 15) << 3;

    float acc[8][8];
#pragma unroll
    for (int i = 0; i < 8; ++i) {
        float bv = bias[m0 + tm + i];
#pragma unroll
        for (int j = 0; j < 8; ++j) acc[i][j] = bv;
    }

    const int kload_m = tid >> 1;            // 0..127
    const int kload_k = (tid & 1) << 2;      // 0 or 4
    const int bload_k = tid >> 5;            // 0..7
    const int bload_n = (tid & 31) << 2;     // 0..124

    for (int kt = 0; kt < Cin; kt += 8) {
        float4 wv = *(const float4*)&W[(size_t)(m0 + kload_m) * Cin + kt + kload_k];
        float a_s = g_A [kt + bload_k];
        float b_s = g_Bc[kt + bload_k];
        float4 xv = *(const float4*)&X[(size_t)(kt + bload_k) * NN + n0 + bload_n];
        sA[kload_k + 0][kload_m] = wv.x;
        sA[kload_k + 1][kload_m] = wv.y;
        sA[kload_k + 2][kload_m] = wv.z;
        sA[kload_k + 3][kload_m] = wv.w;
        float4 yv;
        yv.x = fmaxf(fmaf(a_s, xv.x, b_s), 0.f);
        yv.y = fmaxf(fmaf(a_s, xv.y, b_s), 0.f);
        yv.z = fmaxf(fmaf(a_s, xv.z, b_s), 0.f);
        yv.w = fmaxf(fmaf(a_s, xv.w, b_s), 0.f);
        *(float4*)&sB[bload_k][bload_n] = yv;
        __syncthreads();
#pragma unroll
        for (int kk = 0; kk < 8; ++kk) {
            float av[8], bv[8];
            *(float4*)(av)     = *(const float4*)&sA[kk][tm];
            *(float4*)(av + 4) = *(const float4*)&sA[kk][tm + 4];
            *(float4*)(bv)     = *(const float4*)&sB[kk][tn];
            *(float4*)(bv + 4) = *(const float4*)&sB[kk][tn + 4];
#pragma unroll
            for (int i = 0; i < 8; ++i)
#pragma unroll
                for (int j = 0; j < 8; ++j)
                    acc[i][j] = fmaf(av[i], bv[j], acc[i][j]);
        }
        __syncthreads();
    }

#pragma unroll
    for (int i = 0; i < 8; ++i) {
        size_t row = (size_t)(m0 + tm + i) * NN + n0 + tn;
        float4 v0 = make_float4(acc[i][0], acc[i][1], acc[i][2], acc[i][3]);
        float4 v1 = make_float4(acc[i][4], acc[i][5], acc[i][6], acc[i][7]);
        *(float4*)&Y[row]     = v0;
        *(float4*)&Y[row + 4] = v1;
    }
}

// =====================================================================
// 7) final: y = relu(A3*x3 + B3), max over k (32 contiguous), write out
// =====================================================================
__global__ void __launch_bounds__(256)
finalmax_kernel(float* __restrict__ out)
{
    using namespace cfg;
    int idx = blockIdx.x * 256 + threadIdx.x;   // c*8192 + bs
    int c  = idx >> 13;
    int bs = idx & 8191;
    const float* p = g_x3 + (size_t)c * NN + (size_t)bs * 32;
    float a = g_A[c], bcoef = g_Bc[c];
    float m = 0.f;  // relu outputs are >= 0
#pragma unroll
    for (int i = 0; i < 8; ++i) {
        float4 v = *(const float4*)&p[i * 4];
        m = fmaxf(m, fmaxf(fmaf(a, v.x, bcoef), 0.f));
        m = fmaxf(m, fmaxf(fmaf(a, v.y, bcoef), 0.f));
        m = fmaxf(m, fmaxf(fmaf(a, v.z, bcoef), 0.f));
        m = fmaxf(m, fmaxf(fmaf(a, v.w, bcoef), 0.f));
    }
    int b = bs >> 11, s = bs & 2047;
    out[(size_t)B * 3 * S + ((size_t)b * 256 + c) * S + s] = m;
}

// =====================================================================
// launcher
// =====================================================================
extern "C" void kernel_launch(void* const* d_in, const int* in_sizes, int n_in,
                              void* d_out, int out_size)
{
    using namespace cfg;
    const float* pos   = (const float*)d_in[0];
    const float* feats = (const float*)d_in[1];
    const float* w1 = (const float*)d_in[2];
    const float* b1 = (const float*)d_in[3];
    const float* g1 = (const float*)d_in[4];
    const float* be1 = (const float*)d_in[5];
    const float* w2 = (const float*)d_in[6];
    const float* b2 = (const float*)d_in[7];
    const float* g2 = (const float*)d_in[8];
    const float* be2 = (const float*)d_in[9];
    const float* w3 = (const float*)d_in[10];
    const float* b3 = (const float*)d_in[11];
    const float* g3 = (const float*)d_in[12];
    const float* be3 = (const float*)d_in[13];
    float* out = (float*)d_out;

    fps_kernel<<<B * 8, 1024>>>(pos);
    gather_kernel<<<BS / 256, 256>>>(pos, out);
    ballq_kernel<<<BS / 8, 256>>>(pos);
    layer1_kernel<<<BS / 8, 256>>>(pos, feats, w1, b1);

    stats_part_kernel<1><<<dim3(64, 64), 256>>>();
    stats_fin_kernel<<<1, 256>>>(g1, be1, 64);

    gemm_kernel<2><<<dim3(NN / 128, 1), 256>>>(w2, b2);

    stats_part_kernel<2><<<dim3(64, 128), 256>>>();
    stats_fin_kernel<<<1, 256>>>(g2, be2, 128);

    gemm_kernel<3><<<dim3(NN / 128, 2), 256>>>(w3, b3);

    stats_part_kernel<3><<<dim3(64, 256), 256>>>();
    stats_fin_kernel<<<1, 256>>>(g3, be3, 256);

    finalmax_kernel<<<(256 * BS) / 256, 256>>>(out);
}